// round 14
// baseline (speedup 1.0000x reference)
#include <cuda_runtime.h>
#include <cuda_bf16.h>
#include <math.h>

// Problem constants
#define S_MC   4
#define BATCH  128
#define NN     128
#define F0     64
#define EMBD   64
#define H1     8
#define F1     16
#define F2     2

#define NTH    1024
#define SD     144   // stride for fp32 xs2 tile (layer-2 path)
#define HBD    68    // stride (32-bit words) for all bf16x2 tiles: (4*row+l3)%32 covers
                     // all banks when lanes step 1 row -> conflict-free

// SMEM layout (32-bit word offsets)
#define OFF_X     0          // x0 bf16x2 [n][fpair] (8704 w); after GEMM1: EPB/EP2B/SP
#define OFF_W     18432      // W1^T bf16x2 [c][fpair] (8704 w); later xs2 fp32 [n][c] SD=144
#define OFF_HB    36864      // 8704: h as bf16x2 [c][j-pair], stride 68
#define OFF_MB    45568      // 8704: adj mask as bf16x2 {1.0/0.0} [i][j-pair], stride 68
#define OFF_P1S   54272      // 128
#define OFF_P1D   54400      // 128
#define OFF_B1    54528      // 16
#define OFF_W2T   54544      // 256
#define OFF_H2    54800      // 256
#define OFF_DST2  55056      // 128
#define OFF_MISC  55184      // 16
#define SMEM_FLOATS 55200
#define SMEM_BYTES (SMEM_FLOATS * 4)   // 220800

// sub-offsets inside OFF_X after GEMM1 (x0 dead)
#define OFF_EPB   0          // 512 words: bf16x2 exp(dst) pairs per head
#define OFF_EP2B  512        // 512 words: 0.2-versions
#define OFF_SP    1024       // 2048 floats: float2 {exp(src), exp(0.2 src)} per (head,n)

typedef unsigned long long ull;

#define FFMA2(d, a, b, c) \
    asm("fma.rn.f32x2 %0, %1, %2, %3;" : "=l"(d) : "l"(a), "l"(b), "l"(c))
#define UNPK2(lo, hi, p) \
    asm("mov.b64 {%0, %1}, %2;" : "=f"(lo), "=f"(hi) : "l"(p))
#define PACKBF(d, hi, lo) \
    asm("cvt.rn.bf16x2.f32 %0, %1, %2;" : "=r"(d) : "f"(hi), "f"(lo))
#define HMUL2B(d, a, b) \
    asm("mul.bf16x2 %0, %1, %2;" : "=r"(d) : "r"(a), "r"(b))
#define HMAX2B(d, a, b) \
    asm("max.bf16x2 %0, %1, %2;" : "=r"(d) : "r"(a), "r"(b))
#define MMA_BF16(c0, c1, c2, c3, a0, a1, a2, a3, b0, b1) \
    asm("mma.sync.aligned.m16n8k16.row.col.f32.bf16.bf16.f32 " \
        "{%0,%1,%2,%3}, {%4,%5,%6,%7}, {%8,%9}, {%0,%1,%2,%3};" \
        : "+f"(c0), "+f"(c1), "+f"(c2), "+f"(c3) \
        : "r"(a0), "r"(a1), "r"(a2), "r"(a3), "r"(b0), "r"(b1))

#define ONES2 0x3F803F80u   // bf16x2 {1.0, 1.0}

__device__ float g_partial[S_MC * BATCH * F2];
__device__ int   g_count;

__device__ __forceinline__ float tanh_fast(float x) {
    float y;
    asm("tanh.approx.f32 %0, %1;" : "=f"(y) : "f"(x));
    return y;
}
__device__ __forceinline__ float elu_f(float x) {
    return x > 0.0f ? x : (__expf(x) - 1.0f);
}

__global__ void __launch_bounds__(NTH, 1)
gat_fused_kernel(const float* __restrict__ x,
                 const float* __restrict__ emb,
                 const int*   __restrict__ adj,
                 const float* __restrict__ w1,
                 const float* __restrict__ a_src1,
                 const float* __restrict__ a_dst1,
                 const float* __restrict__ b1,
                 const float* __restrict__ w2,
                 const float* __restrict__ a_src2,
                 const float* __restrict__ a_dst2,
                 const float* __restrict__ b2,
                 float* __restrict__ out)
{
    extern __shared__ float sm[];
    float*    sX    = sm + OFF_X;
    unsigned* sXB   = (unsigned*)(sm + OFF_X);    // x0 bf16x2 [n][fpair]
    float*    sW    = sm + OFF_W;                  // later xs2 fp32
    unsigned* sWB   = (unsigned*)(sm + OFF_W);    // W1^T bf16x2 [c][fpair]
    unsigned* sHB   = (unsigned*)(sm + OFF_HB);
    unsigned* sMB   = (unsigned*)(sm + OFF_MB);
    float*    sP1S  = sm + OFF_P1S;
    float*    sP1D  = sm + OFF_P1D;
    float*    sB1   = sm + OFF_B1;
    float*    sW2T  = sm + OFF_W2T;
    float*    sH2   = sm + OFF_H2;
    float*    sDST2 = sm + OFF_DST2;
    float*    sMISC = sm + OFF_MISC;
    __shared__ int sLast;

    const int tid = threadIdx.x;
    const int sb  = blockIdx.x;
    const int s   = sb >> 7;
    const int b   = sb & 127;
    const int warp = tid >> 5, lane = tid & 31;
    const int g = lane >> 2, l3 = lane & 3;

    // ---- stage x0 = concat(x[b], emb[b]) as bf16x2 [n][fpair] ----
    {
        const float4* xv = (const float4*)(x   + (size_t)b * NN * F0);
        const float4* ev = (const float4*)(emb + (size_t)b * NN * EMBD);
        for (int i = tid; i < NN * 32; i += NTH) {
            int n = i >> 5, c4 = i & 31;
            float4 v = (c4 < 16) ? xv[n * 16 + c4] : ev[n * 16 + (c4 - 16)];
            unsigned lo, hi;
            PACKBF(lo, v.y, v.x);
            PACKBF(hi, v.w, v.z);
            *(ull*)&sXB[n * HBD + c4 * 2] = (ull)lo | ((ull)hi << 32);
        }
    }
    // ---- stage W1[s] transposed as bf16x2 [c][fpair] ----
    {
        const float4* wv = (const float4*)(w1 + (size_t)s * H1 * 128 * F1);
        for (int i = tid; i < 2048; i += NTH) {    // head(8) x fpair(64) x o4(4)
            int head = i >> 8;
            int rem  = i & 255;
            int fp = rem >> 2, o4 = rem & 3;
            int f = fp * 2;
            float4 v0 = wv[(head * 128 + f) * 4 + o4];
            float4 v1 = wv[(head * 128 + f + 1) * 4 + o4];
            int c = head * 16 + o4 * 4;
            unsigned p;
            PACKBF(p, v1.x, v0.x); sWB[(c + 0) * HBD + fp] = p;
            PACKBF(p, v1.y, v0.y); sWB[(c + 1) * HBD + fp] = p;
            PACKBF(p, v1.z, v0.z); sWB[(c + 2) * HBD + fp] = p;
            PACKBF(p, v1.w, v0.w); sWB[(c + 3) * HBD + fp] = p;
        }
    }
    // ---- adjacency mask as packed bf16x2 {1.0/0.0} per j-pair ----
    {
        const int2* arow = (const int2*)(adj + (size_t)b * NN * NN);
        for (int idx = tid; idx < 128 * 64; idx += NTH) {
            int i = idx >> 6, p = idx & 63;
            int2 av = arow[i * 64 + p];
            unsigned w = (av.x ? 0x3F80u : 0u) | (av.y ? 0x3F800000u : 0u);
            sMB[i * HBD + p] = w;
        }
    }
    // ---- small params ----
    if (tid < 128) { sP1S[tid] = a_src1[s * 128 + tid]; sP1D[tid] = a_dst1[s * 128 + tid]; }
    if (tid < 16)  sB1[tid] = b1[tid];
    if (tid < 256) { int f = tid >> 1, o = tid & 1; sW2T[o * 128 + f] = w2[s * 256 + tid]; }
    if (tid == 0) {
        sMISC[0] = a_src2[s * 2 + 0]; sMISC[1] = a_src2[s * 2 + 1];
        sMISC[2] = a_dst2[s * 2 + 0]; sMISC[3] = a_dst2[s * 2 + 1];
        sMISC[4] = b2[0];             sMISC[5] = b2[1];
    }
    __syncthreads();

    // ---- GEMM1 (bf16 m16n8k16, k-outer): hT[c][n] = sum_f W^T[c][f] x0[n][f] ----
    {
        const int ct = (warp >> 2) * 16;
        const int ra = ct + g, rb = ra + 8;
        const unsigned* wra = sWB + ra * HBD;
        const unsigned* wrb = sWB + rb * HBD;
        const int nbase = (warp & 3) * 8;
        float acc[4][4];
#pragma unroll
        for (int q = 0; q < 4; q++)
#pragma unroll
            for (int c = 0; c < 4; c++) acc[q][c] = 0.f;

#pragma unroll
        for (int t = 0; t < 8; t++) {
            const int p0 = 8 * t + l3, p1 = p0 + 4;
            const unsigned a0 = wra[p0];
            const unsigned a1 = wrb[p0];
            const unsigned a2 = wra[p1];
            const unsigned a3 = wrb[p1];
#pragma unroll
            for (int q = 0; q < 4; q++) {
                const int n0 = nbase + 32 * q;
                const unsigned* xb = sXB + (n0 + g) * HBD;
                MMA_BF16(acc[q][0], acc[q][1], acc[q][2], acc[q][3],
                         a0, a1, a2, a3, xb[p0], xb[p1]);
            }
        }
#pragma unroll
        for (int q = 0; q < 4; q++) {
            const int n0 = nbase + 32 * q;
            unsigned wa, wb;
            PACKBF(wa, acc[q][1], acc[q][0]);
            PACKBF(wb, acc[q][3], acc[q][2]);
            sHB[ra * HBD + (n0 >> 1) + l3] = wa;
            sHB[rb * HBD + (n0 >> 1) + l3] = wb;
        }
    }
    __syncthreads();

    // ---- att projections from bf16 h -> packed exp factors ----
    {
        const int head = tid >> 7, n = tid & 127;
        const unsigned* hw = sHB + (head * 16) * HBD + (n >> 1);
        const int amt = (1 - (n & 1)) * 16;
        float sa = 0.0f, da = 0.0f;
#pragma unroll
        for (int o = 0; o < 16; o++) {
            unsigned w = hw[o * HBD];
            float t = tanh_fast(__uint_as_float((w << amt) & 0xFFFF0000u));
            sa += t * sP1S[head * 16 + o];
            da += t * sP1D[head * 16 + o];
        }
        float ed  = __expf(da);
        float ed2 = __expf(0.2f * da);
        float edn  = __shfl_down_sync(0xffffffffu, ed, 1);
        float ed2n = __shfl_down_sync(0xffffffffu, ed2, 1);
        unsigned* EPB  = (unsigned*)(sX + OFF_EPB);
        unsigned* EP2B = (unsigned*)(sX + OFF_EP2B);
        if (!(n & 1)) {
            unsigned w1p, w2p;
            PACKBF(w1p, edn, ed);
            PACKBF(w2p, ed2n, ed2);
            EPB[head * 64 + (n >> 1)]  = w1p;
            EP2B[head * 64 + (n >> 1)] = w2p;
        }
        float2* SP = (float2*)(sX + OFF_SP);
        SP[tid] = make_float2(__expf(sa), __expf(0.2f * sa));
    }
    __syncthreads();

    // ---- flash-style AV: 64 jobs, bf16 m16n8k16 mma; row sums via ones-MMA ----
    {
        const unsigned* EPBb  = (const unsigned*)(sX + OFF_EPB);
        const unsigned* EP2Bb = (const unsigned*)(sX + OFF_EP2B);
        const float2*   SP    = (const float2*)(sX + OFF_SP);
        for (int job = warp; job < 64; job += 32) {
            const int head = job >> 3, rt = job & 7;
            const int i0 = rt * 16;
            const int ra = i0 + g, rb = ra + 8;
            const float2 spaf = SP[head * 128 + ra];
            const float2 spbf = SP[head * 128 + rb];
            unsigned EsA, Es2A, EsB, Es2B;
            PACKBF(EsA,  spaf.x, spaf.x);
            PACKBF(Es2A, spaf.y, spaf.y);
            PACKBF(EsB,  spbf.x, spbf.x);
            PACKBF(Es2B, spbf.y, spbf.y);
            float cA0 = 0.f, cA1 = 0.f, cA2 = 0.f, cA3 = 0.f;
            float cB0 = 0.f, cB1 = 0.f, cB2 = 0.f, cB3 = 0.f;
            float cS0 = 0.f, cS1 = 0.f, cS2 = 0.f, cS3 = 0.f;
            const unsigned* EPh  = EPBb + head * 64;
            const unsigned* EP2h = EP2Bb + head * 64;
            const unsigned* MA = sMB + ra * HBD;
            const unsigned* MBp = sMB + rb * HBD;
            const unsigned* H0 = sHB + (head * 16 + g) * HBD;
            const unsigned* H1p = sHB + (head * 16 + 8 + g) * HBD;
#pragma unroll
            for (int t = 0; t < 8; t++) {
                const int p0 = 8 * t + l3, p1 = p0 + 4;
                const unsigned eb0 = EPh[p0],  eb1 = EPh[p1];
                const unsigned e20 = EP2h[p0], e21 = EP2h[p1];
                const unsigned ma0 = MA[p0],  ma1 = MA[p1];
                const unsigned mb0 = MBp[p0], mb1 = MBp[p1];
                unsigned t0, t1, a0, a1, a2, a3;
                HMUL2B(t0, EsA, eb0); HMUL2B(t1, Es2A, e20);
                HMAX2B(a0, t0, t1);   HMUL2B(a0, a0, ma0);
                HMUL2B(t0, EsB, eb0); HMUL2B(t1, Es2B, e20);
                HMAX2B(a1, t0, t1);   HMUL2B(a1, a1, mb0);
                HMUL2B(t0, EsA, eb1); HMUL2B(t1, Es2A, e21);
                HMAX2B(a2, t0, t1);   HMUL2B(a2, a2, ma1);
                HMUL2B(t0, EsB, eb1); HMUL2B(t1, Es2B, e21);
                HMAX2B(a3, t0, t1);   HMUL2B(a3, a3, mb1);
                const unsigned h00 = H0[p0], h01 = H0[p1];
                const unsigned h10 = H1p[p0], h11 = H1p[p1];
                MMA_BF16(cA0, cA1, cA2, cA3, a0, a1, a2, a3, h00, h01);
                MMA_BF16(cB0, cB1, cB2, cB3, a0, a1, a2, a3, h10, h11);
                MMA_BF16(cS0, cS1, cS2, cS3, a0, a1, a2, a3, ONES2, ONES2);
            }
            const float inva = 1.0f / cS0;
            const float invb = 1.0f / cS2;
            const int cl0 = l3 * 2;
            const float bi00 = sB1[cl0], bi01 = sB1[cl0 + 1];
            const float bi10 = sB1[cl0 + 8], bi11 = sB1[cl0 + 9];
            const int c0c = head * 16;
            *(float2*)&sW[ra * SD + c0c + cl0] =
                make_float2(elu_f(cA0 * inva + bi00), elu_f(cA1 * inva + bi01));
            *(float2*)&sW[ra * SD + c0c + 8 + cl0] =
                make_float2(elu_f(cB0 * inva + bi10), elu_f(cB1 * inva + bi11));
            *(float2*)&sW[rb * SD + c0c + cl0] =
                make_float2(elu_f(cA2 * invb + bi00), elu_f(cA3 * invb + bi01));
            *(float2*)&sW[rb * SD + c0c + 8 + cl0] =
                make_float2(elu_f(cB2 * invb + bi10), elu_f(cB3 * invb + bi11));
        }
    }
    __syncthreads();

    // ---- layer 2 linear: h2[n][0:2], f split 8 ways + shfl reduce ----
    {
        const int n = tid >> 3, fs = tid & 7;
        const float* xr = sW + n * SD + fs * 16;
        const ull* w2o0 = (const ull*)&sW2T[0 * 128 + fs * 16];
        const ull* w2o1 = (const ull*)&sW2T[1 * 128 + fs * 16];
        ull acc0 = 0ULL, acc1 = 0ULL;
#pragma unroll
        for (int fp = 0; fp < 8; fp++) {
            const ull xp = *(const ull*)&xr[fp * 2];
            FFMA2(acc0, xp, w2o0[fp], acc0);
            FFMA2(acc1, xp, w2o1[fp], acc1);
        }
        float l0, h0, l1, h1;
        UNPK2(l0, h0, acc0); UNPK2(l1, h1, acc1);
        float p0 = l0 + h0, p1 = l1 + h1;
#pragma unroll
        for (int d = 4; d > 0; d >>= 1) {
            p0 += __shfl_xor_sync(0xffffffffu, p0, d);
            p1 += __shfl_xor_sync(0xffffffffu, p1, d);
        }
        if (fs == 0) { sH2[2 * n] = p0; sH2[2 * n + 1] = p1; }
    }
    __syncthreads();
    if (tid < 128) {
        int n = tid;
        float t0 = tanh_fast(sH2[2 * n]);
        float t1 = tanh_fast(sH2[2 * n + 1]);
        sDST2[n] = t0 * sMISC[2] + t1 * sMISC[3];
        if (n == 127) sMISC[6] = t0 * sMISC[0] + t1 * sMISC[1];
    }
    __syncthreads();

    // ---- ego-node attention row (i=127): mask-multiplied exp, AV, log_softmax ----
    if (tid < 32) {
        float src = sMISC[6];
        float sum = 0.0f, a0 = 0.0f, a1 = 0.0f;
        const int amt = (1 - (lane & 1)) * 16;
#pragma unroll
        for (int gg = 0; gg < 4; gg++) {
            int j = gg * 32 + lane;
            float v = src + sDST2[j];
            v = fmaxf(v, 0.2f * v);
            unsigned mw = sMB[127 * HBD + (j >> 1)];
            float mf = __uint_as_float((mw << amt) & 0xFFFF0000u);
            float e = __expf(v) * mf;
            sum += e;
            a0 += e * sH2[2 * j];
            a1 += e * sH2[2 * j + 1];
        }
#pragma unroll
        for (int d = 16; d > 0; d >>= 1) {
            sum += __shfl_xor_sync(0xffffffffu, sum, d);
            a0  += __shfl_xor_sync(0xffffffffu, a0, d);
            a1  += __shfl_xor_sync(0xffffffffu, a1, d);
        }
        if (lane == 0) {
            float inv = 1.0f / sum;
            float o0 = a0 * inv + sMISC[4];
            float o1 = a1 * inv + sMISC[5];
            float mm  = fmaxf(o0, o1);
            float lse = mm + logf(expf(o0 - mm) + expf(o1 - mm));
            g_partial[(s * BATCH + b) * 2 + 0] = o0 - lse;
            g_partial[(s * BATCH + b) * 2 + 1] = o1 - lse;
        }
    }

    // ---- last-CTA final reduce (mean over S) ----
    if (tid == 0) {
        __threadfence();
        int old = atomicAdd(&g_count, 1);
        sLast = (old == (S_MC * BATCH - 1)) ? 1 : 0;
    }
    __syncthreads();
    if (sLast) {
        if (tid < 256) {
            const volatile float* gp = g_partial;
            float v = gp[tid] + gp[256 + tid] + gp[512 + tid] + gp[768 + tid];
            out[tid] = 0.25f * v;
        }
        if (tid == 0) g_count = 0;
    }
}

extern "C" void kernel_launch(void* const* d_in, const int* in_sizes, int n_in,
                              void* d_out, int out_size)
{
    const float* x      = (const float*)d_in[0];
    const float* emb    = (const float*)d_in[1];
    const int*   adj    = (const int*)d_in[2];
    const float* w1     = (const float*)d_in[3];
    const float* a_src1 = (const float*)d_in[4];
    const float* a_dst1 = (const float*)d_in[5];
    const float* b1     = (const float*)d_in[6];
    const float* w2     = (const float*)d_in[7];
    const float* a_src2 = (const float*)d_in[8];
    const float* a_dst2 = (const float*)d_in[9];
    const float* b2     = (const float*)d_in[10];

    cudaFuncSetAttribute(gat_fused_kernel,
                         cudaFuncAttributeMaxDynamicSharedMemorySize, SMEM_BYTES);

    gat_fused_kernel<<<S_MC * BATCH, NTH, SMEM_BYTES>>>(
        x, emb, adj, w1, a_src1, a_dst1, b1, w2, a_src2, a_dst2, b2,
        (float*)d_out);
}

// round 15
// speedup vs baseline: 1.5356x; 1.5356x over previous
#include <cuda_runtime.h>
#include <cuda_bf16.h>
#include <math.h>

// Problem constants
#define S_MC   4
#define BATCH  128
#define NN     128
#define F0     64
#define EMBD   64
#define H1     8
#define F1     16
#define F2     2

#define NTH    1024
#define SD     144   // stride for fp32 tiles (x0, W/xs2): conflict-free m16n8k8 lds.128
#define HBD    68    // stride (words) for bf16x2 tiles: (4*row+l3)%32 covers all banks

// SMEM layout (32-bit word offsets)
#define OFF_X0    0          // 18432: x0 tf32 [n][f]  (persists across s)
#define OFF_W     18432      // 18432: W1^T tf32 [c][f] per s; reused as xs2 fp32 [n][c]
#define OFF_HB    36864      // 8704: h bf16x2 [c][j-pair], stride 68 (per s)
#define OFF_MB    45568      // 8704: adj mask bf16x2 {1.0/0.0} [i][j-pair] (persists)
#define OFF_EPB   54272      // 512: bf16x2 exp(dst) pairs per head (per s)
#define OFF_EP2B  54784      // 512: exp(0.2 dst) pairs
#define OFF_SPB   55296      // 512: bf16x2 exp(src) pairs
#define OFF_SP2B  55808      // 512: exp(0.2 src) pairs
#define OFF_P1S   56320      // 128 (per s)
#define OFF_P1D   56448      // 128 (per s)
#define OFF_B1    56576      // 16  (once)
#define OFF_W2T   56592      // 256 (per s)
#define OFF_H2    56848      // 256
#define OFF_DST2  57104      // 128
#define OFF_MISC  57232      // 16
#define SMEM_FLOATS 57248
#define SMEM_BYTES (SMEM_FLOATS * 4)   // 228992 <= 232448 (227KB cap)

typedef unsigned long long ull;

#define FFMA2(d, a, b, c) \
    asm("fma.rn.f32x2 %0, %1, %2, %3;" : "=l"(d) : "l"(a), "l"(b), "l"(c))
#define UNPK2(lo, hi, p) \
    asm("mov.b64 {%0, %1}, %2;" : "=f"(lo), "=f"(hi) : "l"(p))
#define CVT_TF32(u, f) \
    asm("cvt.rna.tf32.f32 %0, %1;" : "=r"(u) : "f"(f))
#define PACKBF(d, hi, lo) \
    asm("cvt.rn.bf16x2.f32 %0, %1, %2;" : "=r"(d) : "f"(hi), "f"(lo))
#define HMUL2B(d, a, b) \
    asm("mul.bf16x2 %0, %1, %2;" : "=r"(d) : "r"(a), "r"(b))
#define HMAX2B(d, a, b) \
    asm("max.bf16x2 %0, %1, %2;" : "=r"(d) : "r"(a), "r"(b))
#define PRMT(d, a, sel) \
    asm("prmt.b32 %0, %1, %1, %2;" : "=r"(d) : "r"(a), "r"(sel))
#define MMA_TF32(c0, c1, c2, c3, a0, a1, a2, a3, b0, b1) \
    asm("mma.sync.aligned.m16n8k8.row.col.f32.tf32.tf32.f32 " \
        "{%0,%1,%2,%3}, {%4,%5,%6,%7}, {%8,%9}, {%0,%1,%2,%3};" \
        : "+f"(c0), "+f"(c1), "+f"(c2), "+f"(c3) \
        : "r"(a0), "r"(a1), "r"(a2), "r"(a3), "r"(b0), "r"(b1))
#define MMA_BF16(c0, c1, c2, c3, a0, a1, a2, a3, b0, b1) \
    asm("mma.sync.aligned.m16n8k16.row.col.f32.bf16.bf16.f32 " \
        "{%0,%1,%2,%3}, {%4,%5,%6,%7}, {%8,%9}, {%0,%1,%2,%3};" \
        : "+f"(c0), "+f"(c1), "+f"(c2), "+f"(c3) \
        : "r"(a0), "r"(a1), "r"(a2), "r"(a3), "r"(b0), "r"(b1))

#define ONES2 0x3F803F80u   // bf16x2 {1.0, 1.0}

__device__ __forceinline__ float tanh_fast(float x) {
    float y;
    asm("tanh.approx.f32 %0, %1;" : "=f"(y) : "f"(x));
    return y;
}
__device__ __forceinline__ float elu_f(float x) {
    return x > 0.0f ? x : (__expf(x) - 1.0f);
}
__device__ __forceinline__ float tf32r(float x) {
    unsigned u; CVT_TF32(u, x); return __uint_as_float(u);
}

__global__ void __launch_bounds__(NTH, 1)
gat_fused_kernel(const float* __restrict__ x,
                 const float* __restrict__ emb,
                 const int*   __restrict__ adj,
                 const float* __restrict__ w1,
                 const float* __restrict__ a_src1,
                 const float* __restrict__ a_dst1,
                 const float* __restrict__ b1,
                 const float* __restrict__ w2,
                 const float* __restrict__ a_src2,
                 const float* __restrict__ a_dst2,
                 const float* __restrict__ b2,
                 float* __restrict__ out)
{
    extern __shared__ float sm[];
    float*    sX0   = sm + OFF_X0;                 // x0 tf32, persists
    float*    sW    = sm + OFF_W;                  // W1^T tf32 / xs2 fp32
    unsigned* sHB   = (unsigned*)(sm + OFF_HB);
    unsigned* sMB   = (unsigned*)(sm + OFF_MB);
    unsigned* EPB   = (unsigned*)(sm + OFF_EPB);
    unsigned* EP2B  = (unsigned*)(sm + OFF_EP2B);
    unsigned* SPB   = (unsigned*)(sm + OFF_SPB);
    unsigned* SP2B  = (unsigned*)(sm + OFF_SP2B);
    float*    sP1S  = sm + OFF_P1S;
    float*    sP1D  = sm + OFF_P1D;
    float*    sB1   = sm + OFF_B1;
    float*    sW2T  = sm + OFF_W2T;
    float*    sH2   = sm + OFF_H2;
    float*    sDST2 = sm + OFF_DST2;
    float*    sMISC = sm + OFF_MISC;

    const int tid = threadIdx.x;
    const int b   = blockIdx.x;
    const int warp = tid >> 5, lane = tid & 31;
    const int g = lane >> 2, l3 = lane & 3;

    // ================= once-per-CTA staging (shared across the 4 MC samples) ====
    // x0 = concat(x[b], emb[b]) rounded to tf32
    {
        const float4* xv = (const float4*)(x   + (size_t)b * NN * F0);
        const float4* ev = (const float4*)(emb + (size_t)b * NN * EMBD);
        for (int i = tid; i < NN * 32; i += NTH) {
            int n = i >> 5, c4 = i & 31;
            float4 v = (c4 < 16) ? xv[n * 16 + c4] : ev[n * 16 + (c4 - 16)];
            v.x = tf32r(v.x); v.y = tf32r(v.y); v.z = tf32r(v.z); v.w = tf32r(v.w);
            *(float4*)&sX0[n * SD + c4 * 4] = v;
        }
    }
    // adjacency mask as packed bf16x2 {1.0/0.0} per j-pair
    {
        const int2* arow = (const int2*)(adj + (size_t)b * NN * NN);
        for (int idx = tid; idx < 128 * 64; idx += NTH) {
            int i = idx >> 6, p = idx & 63;
            int2 av = arow[i * 64 + p];
            unsigned w = (av.x ? 0x3F80u : 0u) | (av.y ? 0x3F800000u : 0u);
            sMB[i * HBD + p] = w;
        }
    }
    if (tid < 16) sB1[tid] = b1[tid];
    if (tid == 0) { sMISC[4] = b2[0]; sMISC[5] = b2[1]; }

    // ================= MC-sample loop ==========================================
    for (int s = 0; s < S_MC; s++) {
        // ---- per-s staging: W1[s]^T (tf32), att params ----
        {
            const float4* wv = (const float4*)(w1 + (size_t)s * H1 * 128 * F1);
            for (int i = tid; i < 4096; i += NTH) {
                int head = i >> 9;
                int rem  = i & 511;
                int f = rem >> 2, o4 = rem & 3;
                float4 v = wv[i];
                int c = head * 16 + o4 * 4;
                sW[(c + 0) * SD + f] = tf32r(v.x);
                sW[(c + 1) * SD + f] = tf32r(v.y);
                sW[(c + 2) * SD + f] = tf32r(v.z);
                sW[(c + 3) * SD + f] = tf32r(v.w);
            }
        }
        if (tid < 128) { sP1S[tid] = a_src1[s * 128 + tid]; sP1D[tid] = a_dst1[s * 128 + tid]; }
        if (tid < 256) { int f = tid >> 1, o = tid & 1; sW2T[o * 128 + f] = w2[s * 256 + tid]; }
        if (tid == 0) {
            sMISC[0] = a_src2[s * 2 + 0]; sMISC[1] = a_src2[s * 2 + 1];
            sMISC[2] = a_dst2[s * 2 + 0]; sMISC[3] = a_dst2[s * 2 + 1];
        }
        __syncthreads();

        // ---- GEMM1 (tf32 tensor, k-outer): hT[c][n] = sum_f wT[c][f] x0[n][f] ----
        {
            const int ct = (warp >> 2) * 16;
            const int ra = ct + g, rb = ra + 8;
            const float* wra = sW + ra * SD;
            const float* wrb = sW + rb * SD;
            const int nbase = (warp & 3) * 8;
            float acc[4][4];
#pragma unroll
            for (int q = 0; q < 4; q++)
#pragma unroll
                for (int c = 0; c < 4; c++) acc[q][c] = 0.f;

#pragma unroll
            for (int t = 0; t < 8; t++) {
                const int o = 16 * t + 4 * l3;
                const float4 A0 = *(const float4*)&wra[o];
                const float4 A1 = *(const float4*)&wrb[o];
#pragma unroll
                for (int q = 0; q < 4; q++) {
                    const int n0 = nbase + 32 * q;
                    const float4 Bv = *(const float4*)&sX0[(n0 + g) * SD + o];
                    MMA_TF32(acc[q][0], acc[q][1], acc[q][2], acc[q][3],
                             __float_as_uint(A0.x), __float_as_uint(A1.x),
                             __float_as_uint(A0.y), __float_as_uint(A1.y),
                             __float_as_uint(Bv.x), __float_as_uint(Bv.y));
                    MMA_TF32(acc[q][0], acc[q][1], acc[q][2], acc[q][3],
                             __float_as_uint(A0.z), __float_as_uint(A1.z),
                             __float_as_uint(A0.w), __float_as_uint(A1.w),
                             __float_as_uint(Bv.z), __float_as_uint(Bv.w));
                }
            }
#pragma unroll
            for (int q = 0; q < 4; q++) {
                const int n0 = nbase + 32 * q;
                unsigned wa, wb;
                PACKBF(wa, acc[q][1], acc[q][0]);
                PACKBF(wb, acc[q][3], acc[q][2]);
                sHB[ra * HBD + (n0 >> 1) + l3] = wa;
                sHB[rb * HBD + (n0 >> 1) + l3] = wb;
            }
        }
        __syncthreads();

        // ---- att projections from bf16 h -> packed exp factors ----
        {
            const int head = tid >> 7, n = tid & 127;
            const unsigned* hw = sHB + (head * 16) * HBD + (n >> 1);
            const int amt = (1 - (n & 1)) * 16;
            float sa = 0.0f, da = 0.0f;
#pragma unroll
            for (int o = 0; o < 16; o++) {
                unsigned w = hw[o * HBD];
                float t = tanh_fast(__uint_as_float((w << amt) & 0xFFFF0000u));
                sa += t * sP1S[head * 16 + o];
                da += t * sP1D[head * 16 + o];
            }
            float ed  = __expf(da);
            float ed2 = __expf(0.2f * da);
            float es  = __expf(sa);
            float es2 = __expf(0.2f * sa);
            float edn  = __shfl_down_sync(0xffffffffu, ed, 1);
            float ed2n = __shfl_down_sync(0xffffffffu, ed2, 1);
            float esn  = __shfl_down_sync(0xffffffffu, es, 1);
            float es2n = __shfl_down_sync(0xffffffffu, es2, 1);
            if (!(n & 1)) {
                unsigned p;
                PACKBF(p, edn,  ed);  EPB[head * 64 + (n >> 1)]  = p;
                PACKBF(p, ed2n, ed2); EP2B[head * 64 + (n >> 1)] = p;
                PACKBF(p, esn,  es);  SPB[head * 64 + (n >> 1)]  = p;
                PACKBF(p, es2n, es2); SP2B[head * 64 + (n >> 1)] = p;
            }
        }
        __syncthreads();

        // ---- flash-style AV: 64 jobs, bf16 m16n8k16; row sums via ones-MMA ----
        {
            for (int job = warp; job < 64; job += 32) {
                const int head = job >> 3, rt = job & 7;
                const int i0 = rt * 16;
                const int ra = i0 + g, rb = ra + 8;
                const unsigned sel = (g & 1) ? 0x3232u : 0x1010u;
                unsigned EsA, Es2A, EsB, Es2B;
                PRMT(EsA,  SPB[head * 64 + (ra >> 1)],      sel);
                PRMT(Es2A, SP2B[head * 64 + (ra >> 1)],     sel);
                PRMT(EsB,  SPB[head * 64 + (ra >> 1) + 4],  sel);
                PRMT(Es2B, SP2B[head * 64 + (ra >> 1) + 4], sel);
                float cA0 = 0.f, cA1 = 0.f, cA2 = 0.f, cA3 = 0.f;
                float cB0 = 0.f, cB1 = 0.f, cB2 = 0.f, cB3 = 0.f;
                float cS0 = 0.f, cS1 = 0.f, cS2 = 0.f, cS3 = 0.f;
                const unsigned* EPh  = EPB + head * 64;
                const unsigned* EP2h = EP2B + head * 64;
                const unsigned* MA  = sMB + ra * HBD;
                const unsigned* MBp = sMB + rb * HBD;
                const unsigned* H0  = sHB + (head * 16 + g) * HBD;
                const unsigned* H1p = sHB + (head * 16 + 8 + g) * HBD;
#pragma unroll
                for (int t = 0; t < 8; t++) {
                    const int p0 = 8 * t + l3, p1 = p0 + 4;
                    const unsigned eb0 = EPh[p0],  eb1 = EPh[p1];
                    const unsigned e20 = EP2h[p0], e21 = EP2h[p1];
                    const unsigned ma0 = MA[p0],  ma1 = MA[p1];
                    const unsigned mb0 = MBp[p0], mb1 = MBp[p1];
                    unsigned t0, t1, a0, a1, a2, a3;
                    HMUL2B(t0, EsA, eb0); HMUL2B(t1, Es2A, e20);
                    HMAX2B(a0, t0, t1);   HMUL2B(a0, a0, ma0);
                    HMUL2B(t0, EsB, eb0); HMUL2B(t1, Es2B, e20);
                    HMAX2B(a1, t0, t1);   HMUL2B(a1, a1, mb0);
                    HMUL2B(t0, EsA, eb1); HMUL2B(t1, Es2A, e21);
                    HMAX2B(a2, t0, t1);   HMUL2B(a2, a2, ma1);
                    HMUL2B(t0, EsB, eb1); HMUL2B(t1, Es2B, e21);
                    HMAX2B(a3, t0, t1);   HMUL2B(a3, a3, mb1);
                    const unsigned h00 = H0[p0], h01 = H0[p1];
                    const unsigned h10 = H1p[p0], h11 = H1p[p1];
                    MMA_BF16(cA0, cA1, cA2, cA3, a0, a1, a2, a3, h00, h01);
                    MMA_BF16(cB0, cB1, cB2, cB3, a0, a1, a2, a3, h10, h11);
                    MMA_BF16(cS0, cS1, cS2, cS3, a0, a1, a2, a3, ONES2, ONES2);
                }
                const float inva = 1.0f / cS0;
                const float invb = 1.0f / cS2;
                const int cl0 = l3 * 2;
                const float bi00 = sB1[cl0], bi01 = sB1[cl0 + 1];
                const float bi10 = sB1[cl0 + 8], bi11 = sB1[cl0 + 9];
                const int c0c = head * 16;
                *(float2*)&sW[ra * SD + c0c + cl0] =
                    make_float2(elu_f(cA0 * inva + bi00), elu_f(cA1 * inva + bi01));
                *(float2*)&sW[ra * SD + c0c + 8 + cl0] =
                    make_float2(elu_f(cB0 * inva + bi10), elu_f(cB1 * inva + bi11));
                *(float2*)&sW[rb * SD + c0c + cl0] =
                    make_float2(elu_f(cA2 * invb + bi00), elu_f(cA3 * invb + bi01));
                *(float2*)&sW[rb * SD + c0c + 8 + cl0] =
                    make_float2(elu_f(cB2 * invb + bi10), elu_f(cB3 * invb + bi11));
            }
        }
        __syncthreads();

        // ---- layer 2 linear: h2[n][0:2], f split 8 ways + shfl reduce ----
        {
            const int n = tid >> 3, fs = tid & 7;
            const float* xr = sW + n * SD + fs * 16;
            const ull* w2o0 = (const ull*)&sW2T[0 * 128 + fs * 16];
            const ull* w2o1 = (const ull*)&sW2T[1 * 128 + fs * 16];
            ull acc0 = 0ULL, acc1 = 0ULL;
#pragma unroll
            for (int fp = 0; fp < 8; fp++) {
                const ull xp = *(const ull*)&xr[fp * 2];
                FFMA2(acc0, xp, w2o0[fp], acc0);
                FFMA2(acc1, xp, w2o1[fp], acc1);
            }
            float l0, h0, l1, h1;
            UNPK2(l0, h0, acc0); UNPK2(l1, h1, acc1);
            float p0 = l0 + h0, p1 = l1 + h1;
#pragma unroll
            for (int d = 4; d > 0; d >>= 1) {
                p0 += __shfl_xor_sync(0xffffffffu, p0, d);
                p1 += __shfl_xor_sync(0xffffffffu, p1, d);
            }
            if (fs == 0) { sH2[2 * n] = p0; sH2[2 * n + 1] = p1; }
        }
        __syncthreads();
        if (tid < 128) {
            int n = tid;
            float t0 = tanh_fast(sH2[2 * n]);
            float t1 = tanh_fast(sH2[2 * n + 1]);
            sDST2[n] = t0 * sMISC[2] + t1 * sMISC[3];
            if (n == 127) sMISC[6] = t0 * sMISC[0] + t1 * sMISC[1];
        }
        __syncthreads();

        // ---- ego-node attention row (i=127): softmax, AV, log_softmax, accum ----
        if (tid < 32) {
            float src = sMISC[6];
            float sum = 0.0f, a0 = 0.0f, a1 = 0.0f;
            const int amt = (1 - (lane & 1)) * 16;
#pragma unroll
            for (int gg = 0; gg < 4; gg++) {
                int j = gg * 32 + lane;
                float v = src + sDST2[j];
                v = fmaxf(v, 0.2f * v);
                unsigned mw = sMB[127 * HBD + (j >> 1)];
                float mf = __uint_as_float((mw << amt) & 0xFFFF0000u);
                float e = __expf(v) * mf;
                sum += e;
                a0 += e * sH2[2 * j];
                a1 += e * sH2[2 * j + 1];
            }
#pragma unroll
            for (int d = 16; d > 0; d >>= 1) {
                sum += __shfl_xor_sync(0xffffffffu, sum, d);
                a0  += __shfl_xor_sync(0xffffffffu, a0, d);
                a1  += __shfl_xor_sync(0xffffffffu, a1, d);
            }
            if (lane == 0) {
                float inv = 1.0f / sum;
                float o0 = a0 * inv + sMISC[4];
                float o1 = a1 * inv + sMISC[5];
                float mm  = fmaxf(o0, o1);
                float lse = mm + logf(expf(o0 - mm) + expf(o1 - mm));
                if (s == 0) { sMISC[8] = o0 - lse;  sMISC[9] = o1 - lse; }
                else        { sMISC[8] += o0 - lse; sMISC[9] += o1 - lse; }
            }
        }
        __syncthreads();   // loop-end: protects W/HB/EP/param regions for next s
    }

    // ---- final: mean over S, direct store (no atomics, fully deterministic) ----
    if (tid == 0) {
        out[b * 2 + 0] = 0.25f * sMISC[8];
        out[b * 2 + 1] = 0.25f * sMISC[9];
    }
}

extern "C" void kernel_launch(void* const* d_in, const int* in_sizes, int n_in,
                              void* d_out, int out_size)
{
    const float* x      = (const float*)d_in[0];
    const float* emb    = (const float*)d_in[1];
    const int*   adj    = (const int*)d_in[2];
    const float* w1     = (const float*)d_in[3];
    const float* a_src1 = (const float*)d_in[4];
    const float* a_dst1 = (const float*)d_in[5];
    const float* b1     = (const float*)d_in[6];
    const float* w2     = (const float*)d_in[7];
    const float* a_src2 = (const float*)d_in[8];
    const float* a_dst2 = (const float*)d_in[9];
    const float* b2     = (const float*)d_in[10];

    cudaFuncSetAttribute(gat_fused_kernel,
                         cudaFuncAttributeMaxDynamicSharedMemorySize, SMEM_BYTES);

    gat_fused_kernel<<<BATCH, NTH, SMEM_BYTES>>>(
        x, emb, adj, w1, a_src1, a_dst1, b1, w2, a_src2, a_dst2, b2,
        (float*)d_out);
}

// round 16
// speedup vs baseline: 1.7447x; 1.1362x over previous
#include <cuda_runtime.h>
#include <cuda_bf16.h>
#include <math.h>

// Problem constants
#define S_MC   4
#define BATCH  128
#define NN     128
#define F0     64
#define EMBD   64
#define H1     8
#define F1     16
#define F2     2

#define NTH    1024
#define SD     144   // stride for fp32 tiles (x0, W): conflict-free m16n8k8 lds.128
#define XSD    136   // stride for fp32 xs2 tile: 136%32=8 -> layer-2 reads hit all 32 banks
#define HBD    68    // stride (words) for bf16x2 tiles: (4*row+l3)%32 covers all banks

// SMEM layout (32-bit word offsets)
#define OFF_X0    0          // 18432: x0 tf32 [n][f]  (persists across s)
#define OFF_W     18432      // 18432: W1^T tf32 [c][f] per s; reused as xs2 fp32 [n][c] XSD
#define OFF_HB    36864      // 8704: h bf16x2 [c][j-pair], stride 68 (per s)
#define OFF_MB    45568      // 8704: adj mask bf16x2 {1.0/0.0} [i][j-pair] (persists)
#define OFF_EPB   54272      // 512: bf16x2 exp(dst) pairs per head (per s)
#define OFF_EP2B  54784      // 512: exp(0.2 dst) pairs
#define OFF_SPB   55296      // 512: bf16x2 exp(src) pairs
#define OFF_SP2B  55808      // 512: exp(0.2 src) pairs
#define OFF_P1S   56320      // 128 (per s)
#define OFF_P1D   56448      // 128 (per s)
#define OFF_B1    56576      // 16  (once)
#define OFF_W2T   56592      // 256 (per s)
#define OFF_H2    56848      // 256
#define OFF_DST2  57104      // 128
#define OFF_MISC  57232      // 16
#define SMEM_FLOATS 57248
#define SMEM_BYTES (SMEM_FLOATS * 4)   // 228992 <= 232448 (227KB cap)

typedef unsigned long long ull;

#define FFMA2(d, a, b, c) \
    asm("fma.rn.f32x2 %0, %1, %2, %3;" : "=l"(d) : "l"(a), "l"(b), "l"(c))
#define UNPK2(lo, hi, p) \
    asm("mov.b64 {%0, %1}, %2;" : "=f"(lo), "=f"(hi) : "l"(p))
#define CVT_TF32(u, f) \
    asm("cvt.rna.tf32.f32 %0, %1;" : "=r"(u) : "f"(f))
#define PACKBF(d, hi, lo) \
    asm("cvt.rn.bf16x2.f32 %0, %1, %2;" : "=r"(d) : "f"(hi), "f"(lo))
#define HMUL2B(d, a, b) \
    asm("mul.bf16x2 %0, %1, %2;" : "=r"(d) : "r"(a), "r"(b))
#define HMAX2B(d, a, b) \
    asm("max.bf16x2 %0, %1, %2;" : "=r"(d) : "r"(a), "r"(b))
#define PRMT(d, a, sel) \
    asm("prmt.b32 %0, %1, %1, %2;" : "=r"(d) : "r"(a), "r"(sel))
#define MMA_TF32(c0, c1, c2, c3, a0, a1, a2, a3, b0, b1) \
    asm("mma.sync.aligned.m16n8k8.row.col.f32.tf32.tf32.f32 " \
        "{%0,%1,%2,%3}, {%4,%5,%6,%7}, {%8,%9}, {%0,%1,%2,%3};" \
        : "+f"(c0), "+f"(c1), "+f"(c2), "+f"(c3) \
        : "r"(a0), "r"(a1), "r"(a2), "r"(a3), "r"(b0), "r"(b1))
#define MMA_BF16(c0, c1, c2, c3, a0, a1, a2, a3, b0, b1) \
    asm("mma.sync.aligned.m16n8k16.row.col.f32.bf16.bf16.f32 " \
        "{%0,%1,%2,%3}, {%4,%5,%6,%7}, {%8,%9}, {%0,%1,%2,%3};" \
        : "+f"(c0), "+f"(c1), "+f"(c2), "+f"(c3) \
        : "r"(a0), "r"(a1), "r"(a2), "r"(a3), "r"(b0), "r"(b1))

#define ONES2 0x3F803F80u   // bf16x2 {1.0, 1.0}

__device__ __forceinline__ float tanh_fast(float x) {
    float y;
    asm("tanh.approx.f32 %0, %1;" : "=f"(y) : "f"(x));
    return y;
}
__device__ __forceinline__ float elu_f(float x) {
    return x > 0.0f ? x : (__expf(x) - 1.0f);
}
__device__ __forceinline__ float tf32r(float x) {
    unsigned u; CVT_TF32(u, x); return __uint_as_float(u);
}

__global__ void __launch_bounds__(NTH, 1)
gat_fused_kernel(const float* __restrict__ x,
                 const float* __restrict__ emb,
                 const int*   __restrict__ adj,
                 const float* __restrict__ w1,
                 const float* __restrict__ a_src1,
                 const float* __restrict__ a_dst1,
                 const float* __restrict__ b1,
                 const float* __restrict__ w2,
                 const float* __restrict__ a_src2,
                 const float* __restrict__ a_dst2,
                 const float* __restrict__ b2,
                 float* __restrict__ out)
{
    extern __shared__ float sm[];
    float*    sX0   = sm + OFF_X0;                 // x0 tf32, persists
    float*    sW    = sm + OFF_W;                  // W1^T tf32 / xs2 fp32 (XSD stride)
    unsigned* sHB   = (unsigned*)(sm + OFF_HB);
    unsigned* sMB   = (unsigned*)(sm + OFF_MB);
    unsigned* EPB   = (unsigned*)(sm + OFF_EPB);
    unsigned* EP2B  = (unsigned*)(sm + OFF_EP2B);
    unsigned* SPB   = (unsigned*)(sm + OFF_SPB);
    unsigned* SP2B  = (unsigned*)(sm + OFF_SP2B);
    float*    sP1S  = sm + OFF_P1S;
    float*    sP1D  = sm + OFF_P1D;
    float*    sB1   = sm + OFF_B1;
    float*    sW2T  = sm + OFF_W2T;
    float*    sH2   = sm + OFF_H2;
    float*    sDST2 = sm + OFF_DST2;
    float*    sMISC = sm + OFF_MISC;

    const int tid = threadIdx.x;
    const int b   = blockIdx.x;
    const int warp = tid >> 5, lane = tid & 31;
    const int g = lane >> 2, l3 = lane & 3;

    // ================= once-per-CTA staging (shared across the 4 MC samples) ====
    // x0 = concat(x[b], emb[b]) rounded to tf32
    {
        const float4* xv = (const float4*)(x   + (size_t)b * NN * F0);
        const float4* ev = (const float4*)(emb + (size_t)b * NN * EMBD);
        for (int i = tid; i < NN * 32; i += NTH) {
            int n = i >> 5, c4 = i & 31;
            float4 v = (c4 < 16) ? xv[n * 16 + c4] : ev[n * 16 + (c4 - 16)];
            v.x = tf32r(v.x); v.y = tf32r(v.y); v.z = tf32r(v.z); v.w = tf32r(v.w);
            *(float4*)&sX0[n * SD + c4 * 4] = v;
        }
    }
    // adjacency mask as packed bf16x2 {1.0/0.0} per j-pair
    {
        const int2* arow = (const int2*)(adj + (size_t)b * NN * NN);
        for (int idx = tid; idx < 128 * 64; idx += NTH) {
            int i = idx >> 6, p = idx & 63;
            int2 av = arow[i * 64 + p];
            unsigned w = (av.x ? 0x3F80u : 0u) | (av.y ? 0x3F800000u : 0u);
            sMB[i * HBD + p] = w;
        }
    }
    if (tid < 16) sB1[tid] = b1[tid];
    if (tid == 0) { sMISC[4] = b2[0]; sMISC[5] = b2[1]; }

    // ================= MC-sample loop ==========================================
    for (int s = 0; s < S_MC; s++) {
        // ---- per-s staging: W1[s]^T (tf32), att params ----
        {
            const float4* wv = (const float4*)(w1 + (size_t)s * H1 * 128 * F1);
            for (int i = tid; i < 4096; i += NTH) {
                int head = i >> 9;
                int rem  = i & 511;
                int f = rem >> 2, o4 = rem & 3;
                float4 v = wv[i];
                int c = head * 16 + o4 * 4;
                sW[(c + 0) * SD + f] = tf32r(v.x);
                sW[(c + 1) * SD + f] = tf32r(v.y);
                sW[(c + 2) * SD + f] = tf32r(v.z);
                sW[(c + 3) * SD + f] = tf32r(v.w);
            }
        }
        if (tid < 128) { sP1S[tid] = a_src1[s * 128 + tid]; sP1D[tid] = a_dst1[s * 128 + tid]; }
        if (tid < 256) { int f = tid >> 1, o = tid & 1; sW2T[o * 128 + f] = w2[s * 256 + tid]; }
        if (tid == 0) {
            sMISC[0] = a_src2[s * 2 + 0]; sMISC[1] = a_src2[s * 2 + 1];
            sMISC[2] = a_dst2[s * 2 + 0]; sMISC[3] = a_dst2[s * 2 + 1];
        }
        __syncthreads();

        // ---- GEMM1 (tf32 tensor, k-outer): hT[c][n] = sum_f wT[c][f] x0[n][f] ----
        {
            const int ct = (warp >> 2) * 16;
            const int ra = ct + g, rb = ra + 8;
            const float* wra = sW + ra * SD;
            const float* wrb = sW + rb * SD;
            const int nbase = (warp & 3) * 8;
            float acc[4][4];
#pragma unroll
            for (int q = 0; q < 4; q++)
#pragma unroll
                for (int c = 0; c < 4; c++) acc[q][c] = 0.f;

#pragma unroll
            for (int t = 0; t < 8; t++) {
                const int o = 16 * t + 4 * l3;
                const float4 A0 = *(const float4*)&wra[o];
                const float4 A1 = *(const float4*)&wrb[o];
#pragma unroll
                for (int q = 0; q < 4; q++) {
                    const int n0 = nbase + 32 * q;
                    const float4 Bv = *(const float4*)&sX0[(n0 + g) * SD + o];
                    MMA_TF32(acc[q][0], acc[q][1], acc[q][2], acc[q][3],
                             __float_as_uint(A0.x), __float_as_uint(A1.x),
                             __float_as_uint(A0.y), __float_as_uint(A1.y),
                             __float_as_uint(Bv.x), __float_as_uint(Bv.y));
                    MMA_TF32(acc[q][0], acc[q][1], acc[q][2], acc[q][3],
                             __float_as_uint(A0.z), __float_as_uint(A1.z),
                             __float_as_uint(A0.w), __float_as_uint(A1.w),
                             __float_as_uint(Bv.z), __float_as_uint(Bv.w));
                }
            }
#pragma unroll
            for (int q = 0; q < 4; q++) {
                const int n0 = nbase + 32 * q;
                unsigned wa, wb;
                PACKBF(wa, acc[q][1], acc[q][0]);
                PACKBF(wb, acc[q][3], acc[q][2]);
                sHB[ra * HBD + (n0 >> 1) + l3] = wa;
                sHB[rb * HBD + (n0 >> 1) + l3] = wb;
            }
        }
        __syncthreads();

        // ---- att projections from bf16 h -> packed exp factors ----
        {
            const int head = tid >> 7, n = tid & 127;
            const unsigned* hw = sHB + (head * 16) * HBD + (n >> 1);
            const int amt = (1 - (n & 1)) * 16;
            float sa = 0.0f, da = 0.0f;
#pragma unroll
            for (int o = 0; o < 16; o++) {
                unsigned w = hw[o * HBD];
                float t = tanh_fast(__uint_as_float((w << amt) & 0xFFFF0000u));
                sa += t * sP1S[head * 16 + o];
                da += t * sP1D[head * 16 + o];
            }
            float ed  = __expf(da);
            float ed2 = __expf(0.2f * da);
            float es  = __expf(sa);
            float es2 = __expf(0.2f * sa);
            float edn  = __shfl_down_sync(0xffffffffu, ed, 1);
            float ed2n = __shfl_down_sync(0xffffffffu, ed2, 1);
            float esn  = __shfl_down_sync(0xffffffffu, es, 1);
            float es2n = __shfl_down_sync(0xffffffffu, es2, 1);
            if (!(n & 1)) {
                unsigned p;
                PACKBF(p, edn,  ed);  EPB[head * 64 + (n >> 1)]  = p;
                PACKBF(p, ed2n, ed2); EP2B[head * 64 + (n >> 1)] = p;
                PACKBF(p, esn,  es);  SPB[head * 64 + (n >> 1)]  = p;
                PACKBF(p, es2n, es2); SP2B[head * 64 + (n >> 1)] = p;
            }
        }
        __syncthreads();

        // ---- flash-style AV: 64 jobs, bf16 m16n8k16; row sums via ones-MMA ----
        {
            for (int job = warp; job < 64; job += 32) {
                const int head = job >> 3, rt = job & 7;
                const int i0 = rt * 16;
                const int ra = i0 + g, rb = ra + 8;
                const unsigned sel = (g & 1) ? 0x3232u : 0x1010u;
                unsigned EsA, Es2A, EsB, Es2B;
                PRMT(EsA,  SPB[head * 64 + (ra >> 1)],      sel);
                PRMT(Es2A, SP2B[head * 64 + (ra >> 1)],     sel);
                PRMT(EsB,  SPB[head * 64 + (ra >> 1) + 4],  sel);
                PRMT(Es2B, SP2B[head * 64 + (ra >> 1) + 4], sel);
                float cA0 = 0.f, cA1 = 0.f, cA2 = 0.f, cA3 = 0.f;
                float cB0 = 0.f, cB1 = 0.f, cB2 = 0.f, cB3 = 0.f;
                float cS0 = 0.f, cS1 = 0.f, cS2 = 0.f, cS3 = 0.f;
                const unsigned* EPh  = EPB + head * 64;
                const unsigned* EP2h = EP2B + head * 64;
                const unsigned* MA  = sMB + ra * HBD;
                const unsigned* MBp = sMB + rb * HBD;
                const unsigned* H0  = sHB + (head * 16 + g) * HBD;
                const unsigned* H1p = sHB + (head * 16 + 8 + g) * HBD;
#pragma unroll
                for (int t = 0; t < 8; t++) {
                    const int p0 = 8 * t + l3, p1 = p0 + 4;
                    const unsigned eb0 = EPh[p0],  eb1 = EPh[p1];
                    const unsigned e20 = EP2h[p0], e21 = EP2h[p1];
                    const unsigned ma0 = MA[p0],  ma1 = MA[p1];
                    const unsigned mb0 = MBp[p0], mb1 = MBp[p1];
                    unsigned t0, t1, a0, a1, a2, a3;
                    HMUL2B(t0, EsA, eb0); HMUL2B(t1, Es2A, e20);
                    HMAX2B(a0, t0, t1);   HMUL2B(a0, a0, ma0);
                    HMUL2B(t0, EsB, eb0); HMUL2B(t1, Es2B, e20);
                    HMAX2B(a1, t0, t1);   HMUL2B(a1, a1, mb0);
                    HMUL2B(t0, EsA, eb1); HMUL2B(t1, Es2A, e21);
                    HMAX2B(a2, t0, t1);   HMUL2B(a2, a2, ma1);
                    HMUL2B(t0, EsB, eb1); HMUL2B(t1, Es2B, e21);
                    HMAX2B(a3, t0, t1);   HMUL2B(a3, a3, mb1);
                    const unsigned h00 = H0[p0], h01 = H0[p1];
                    const unsigned h10 = H1p[p0], h11 = H1p[p1];
                    MMA_BF16(cA0, cA1, cA2, cA3, a0, a1, a2, a3, h00, h01);
                    MMA_BF16(cB0, cB1, cB2, cB3, a0, a1, a2, a3, h10, h11);
                    MMA_BF16(cS0, cS1, cS2, cS3, a0, a1, a2, a3, ONES2, ONES2);
                }
                const float inva = 1.0f / cS0;
                const float invb = 1.0f / cS2;
                const int cl0 = l3 * 2;
                const float bi00 = sB1[cl0], bi01 = sB1[cl0 + 1];
                const float bi10 = sB1[cl0 + 8], bi11 = sB1[cl0 + 9];
                const int c0c = head * 16;
                *(float2*)&sW[ra * XSD + c0c + cl0] =
                    make_float2(elu_f(cA0 * inva + bi00), elu_f(cA1 * inva + bi01));
                *(float2*)&sW[ra * XSD + c0c + 8 + cl0] =
                    make_float2(elu_f(cB0 * inva + bi10), elu_f(cB1 * inva + bi11));
                *(float2*)&sW[rb * XSD + c0c + cl0] =
                    make_float2(elu_f(cA2 * invb + bi00), elu_f(cA3 * invb + bi01));
                *(float2*)&sW[rb * XSD + c0c + 8 + cl0] =
                    make_float2(elu_f(cB2 * invb + bi10), elu_f(cB3 * invb + bi11));
            }
        }
        __syncthreads();

        // ---- layer 2 linear: h2[n][0:2], interleaved f split (conflict-free) ----
        // Thread (n, fs) covers f in {2fs + 16k, 2fs+1 + 16k}, k=0..7.
        // Bank = 8n + 2fs + 16fp (mod 32): all 32 lanes distinct -> no conflicts.
        {
            const int n = tid >> 3, fs = tid & 7;
            const float* xr = sW + n * XSD + fs * 2;
            const ull* w2o0 = (const ull*)&sW2T[0 * 128];
            const ull* w2o1 = (const ull*)&sW2T[1 * 128];
            ull acc0 = 0ULL, acc1 = 0ULL;
#pragma unroll
            for (int fp = 0; fp < 8; fp++) {
                const ull xp = *(const ull*)&xr[fp * 16];
                FFMA2(acc0, xp, w2o0[fs + fp * 8], acc0);
                FFMA2(acc1, xp, w2o1[fs + fp * 8], acc1);
            }
            float l0, h0, l1, h1;
            UNPK2(l0, h0, acc0); UNPK2(l1, h1, acc1);
            float p0 = l0 + h0, p1 = l1 + h1;
#pragma unroll
            for (int d = 4; d > 0; d >>= 1) {
                p0 += __shfl_xor_sync(0xffffffffu, p0, d);
                p1 += __shfl_xor_sync(0xffffffffu, p1, d);
            }
            if (fs == 0) { sH2[2 * n] = p0; sH2[2 * n + 1] = p1; }
        }
        __syncthreads();
        if (tid < 128) {
            int n = tid;
            float t0 = tanh_fast(sH2[2 * n]);
            float t1 = tanh_fast(sH2[2 * n + 1]);
            sDST2[n] = t0 * sMISC[2] + t1 * sMISC[3];
            if (n == 127) sMISC[6] = t0 * sMISC[0] + t1 * sMISC[1];
        }
        __syncthreads();

        // ---- ego-node attention row (i=127): softmax, AV, log_softmax, accum ----
        if (tid < 32) {
            float src = sMISC[6];
            float sum = 0.0f, a0 = 0.0f, a1 = 0.0f;
            const int amt = (1 - (lane & 1)) * 16;
#pragma unroll
            for (int gg = 0; gg < 4; gg++) {
                int j = gg * 32 + lane;
                float v = src + sDST2[j];
                v = fmaxf(v, 0.2f * v);
                unsigned mw = sMB[127 * HBD + (j >> 1)];
                float mf = __uint_as_float((mw << amt) & 0xFFFF0000u);
                float e = __expf(v) * mf;
                sum += e;
                a0 += e * sH2[2 * j];
                a1 += e * sH2[2 * j + 1];
            }
#pragma unroll
            for (int d = 16; d > 0; d >>= 1) {
                sum += __shfl_xor_sync(0xffffffffu, sum, d);
                a0  += __shfl_xor_sync(0xffffffffu, a0, d);
                a1  += __shfl_xor_sync(0xffffffffu, a1, d);
            }
            if (lane == 0) {
                float inv = 1.0f / sum;
                float o0 = a0 * inv + sMISC[4];
                float o1 = a1 * inv + sMISC[5];
                float mm  = fmaxf(o0, o1);
                float lse = mm + logf(expf(o0 - mm) + expf(o1 - mm));
                if (s == 0) { sMISC[8] = o0 - lse;  sMISC[9] = o1 - lse; }
                else        { sMISC[8] += o0 - lse; sMISC[9] += o1 - lse; }
            }
        }
        __syncthreads();   // loop-end: protects W/HB/EP/param regions for next s
    }

    // ---- final: mean over S, direct store (no atomics, fully deterministic) ----
    if (tid == 0) {
        out[b * 2 + 0] = 0.25f * sMISC[8];
        out[b * 2 + 1] = 0.25f * sMISC[9];
    }
}

extern "C" void kernel_launch(void* const* d_in, const int* in_sizes, int n_in,
                              void* d_out, int out_size)
{
    const float* x      = (const float*)d_in[0];
    const float* emb    = (const float*)d_in[1];
    const int*   adj    = (const int*)d_in[2];
    const float* w1     = (const float*)d_in[3];
    const float* a_src1 = (const float*)d_in[4];
    const float* a_dst1 = (const float*)d_in[5];
    const float* b1     = (const float*)d_in[6];
    const float* w2     = (const float*)d_in[7];
    const float* a_src2 = (const float*)d_in[8];
    const float* a_dst2 = (const float*)d_in[9];
    const float* b2     = (const float*)d_in[10];

    cudaFuncSetAttribute(gat_fused_kernel,
                         cudaFuncAttributeMaxDynamicSharedMemorySize, SMEM_BYTES);

    gat_fused_kernel<<<BATCH, NTH, SMEM_BYTES>>>(
        x, emb, adj, w1, a_src1, a_dst1, b1, w2, a_src2, a_dst2, b2,
        (float*)d_out);
}

// round 17
// speedup vs baseline: 1.8082x; 1.0364x over previous
#include <cuda_runtime.h>
#include <cuda_bf16.h>
#include <math.h>

// Problem constants
#define S_MC   4
#define BATCH  128
#define NN     128
#define F0     64
#define EMBD   64
#define H1     8
#define F1     16
#define F2     2

#define NTH    1024
#define SD     144   // stride for fp32 tiles (x0, W): conflict-free m16n8k8 lds.128
#define XSD    136   // stride for fp32 xs2 tile: layer-2 reads hit all 32 banks
#define HBD    68    // stride (words) for bf16x2 tiles: (4*row+l3)%32 covers all banks

// SMEM layout (32-bit word offsets)
#define OFF_X0    0          // 18432: x0 tf32 [n][f]  (persists across s)
#define OFF_W     18432      // 18432: W1^T tf32 [c][f] per s; reused as xs2 fp32 [n][c] XSD
#define OFF_HB    36864      // 8704: h bf16x2 [c][j-pair], stride 68 (per s)
#define OFF_MB    45568      // 8704: adj mask bf16x2 {1.0/0.0} [i][j-pair] (persists)
#define OFF_EI    54272      // 1024: interleaved {exp(dst), exp(.2dst)} bf16x2 per pair
#define OFF_SI    55296      // 1024: interleaved {exp(src), exp(.2src)} bf16x2 per pair
#define OFF_P1S   56320      // 128 (per s)
#define OFF_P1D   56448      // 128 (per s)
#define OFF_B1    56576      // 16  (once)
#define OFF_W2T   56592      // 256 (per s)
#define OFF_H2    56848      // 256
#define OFF_MISC  57104      // 16: [0..3]=as2/ad2 slot0, [4..7]=slot1, [8,9]=b2, [10,11]=acc
#define SMEM_FLOATS 57120
#define SMEM_BYTES (SMEM_FLOATS * 4)   // 228480 <= 232448

typedef unsigned long long ull;

#define FFMA2(d, a, b, c) \
    asm("fma.rn.f32x2 %0, %1, %2, %3;" : "=l"(d) : "l"(a), "l"(b), "l"(c))
#define UNPK2(lo, hi, p) \
    asm("mov.b64 {%0, %1}, %2;" : "=f"(lo), "=f"(hi) : "l"(p))
#define CVT_TF32(u, f) \
    asm("cvt.rna.tf32.f32 %0, %1;" : "=r"(u) : "f"(f))
#define PACKBF(d, hi, lo) \
    asm("cvt.rn.bf16x2.f32 %0, %1, %2;" : "=r"(d) : "f"(hi), "f"(lo))
#define HMUL2B(d, a, b) \
    asm("mul.bf16x2 %0, %1, %2;" : "=r"(d) : "r"(a), "r"(b))
#define HMAX2B(d, a, b) \
    asm("max.bf16x2 %0, %1, %2;" : "=r"(d) : "r"(a), "r"(b))
#define PRMT(d, a, sel) \
    asm("prmt.b32 %0, %1, %1, %2;" : "=r"(d) : "r"(a), "r"(sel))
#define MMA_TF32(c0, c1, c2, c3, a0, a1, a2, a3, b0, b1) \
    asm("mma.sync.aligned.m16n8k8.row.col.f32.tf32.tf32.f32 " \
        "{%0,%1,%2,%3}, {%4,%5,%6,%7}, {%8,%9}, {%0,%1,%2,%3};" \
        : "+f"(c0), "+f"(c1), "+f"(c2), "+f"(c3) \
        : "r"(a0), "r"(a1), "r"(a2), "r"(a3), "r"(b0), "r"(b1))
#define MMA_BF16(c0, c1, c2, c3, a0, a1, a2, a3, b0, b1) \
    asm("mma.sync.aligned.m16n8k16.row.col.f32.bf16.bf16.f32 " \
        "{%0,%1,%2,%3}, {%4,%5,%6,%7}, {%8,%9}, {%0,%1,%2,%3};" \
        : "+f"(c0), "+f"(c1), "+f"(c2), "+f"(c3) \
        : "r"(a0), "r"(a1), "r"(a2), "r"(a3), "r"(b0), "r"(b1))

#define ONES2 0x3F803F80u   // bf16x2 {1.0, 1.0}

__device__ __forceinline__ float tanh_fast(float x) {
    float y;
    asm("tanh.approx.f32 %0, %1;" : "=f"(y) : "f"(x));
    return y;
}
__device__ __forceinline__ float elu_f(float x) {
    return x > 0.0f ? x : (__expf(x) - 1.0f);
}
__device__ __forceinline__ float tf32r(float x) {
    unsigned u; CVT_TF32(u, x); return __uint_as_float(u);
}

__global__ void __launch_bounds__(NTH, 1)
gat_fused_kernel(const float* __restrict__ x,
                 const float* __restrict__ emb,
                 const int*   __restrict__ adj,
                 const float* __restrict__ w1,
                 const float* __restrict__ a_src1,
                 const float* __restrict__ a_dst1,
                 const float* __restrict__ b1,
                 const float* __restrict__ w2,
                 const float* __restrict__ a_src2,
                 const float* __restrict__ a_dst2,
                 const float* __restrict__ b2,
                 float* __restrict__ out)
{
    extern __shared__ float sm[];
    float*    sX0   = sm + OFF_X0;                 // x0 tf32, persists
    float*    sW    = sm + OFF_W;                  // W1^T tf32 / xs2 fp32 (XSD stride)
    unsigned* sHB   = (unsigned*)(sm + OFF_HB);
    unsigned* sMB   = (unsigned*)(sm + OFF_MB);
    ull*      sEI   = (ull*)(sm + OFF_EI);         // 512 entries: {eb, e2} packed
    ull*      sSI   = (ull*)(sm + OFF_SI);         // 512 entries: {es, es2} packed
    float*    sP1S  = sm + OFF_P1S;
    float*    sP1D  = sm + OFF_P1D;
    float*    sB1   = sm + OFF_B1;
    float*    sW2T  = sm + OFF_W2T;
    float*    sH2   = sm + OFF_H2;
    float*    sMISC = sm + OFF_MISC;

    const int tid = threadIdx.x;
    const int b   = blockIdx.x;
    const int warp = tid >> 5, lane = tid & 31;
    const int g = lane >> 2, l3 = lane & 3;

    // ================= once-per-CTA staging =====================================
    // x0 = concat(x[b], emb[b]) rounded to tf32
    {
        const float4* xv = (const float4*)(x   + (size_t)b * NN * F0);
        const float4* ev = (const float4*)(emb + (size_t)b * NN * EMBD);
        for (int i = tid; i < NN * 32; i += NTH) {
            int n = i >> 5, c4 = i & 31;
            float4 v = (c4 < 16) ? xv[n * 16 + c4] : ev[n * 16 + (c4 - 16)];
            v.x = tf32r(v.x); v.y = tf32r(v.y); v.z = tf32r(v.z); v.w = tf32r(v.w);
            *(float4*)&sX0[n * SD + c4 * 4] = v;
        }
    }
    // adjacency mask as packed bf16x2 {1.0/0.0} per j-pair
    {
        const int2* arow = (const int2*)(adj + (size_t)b * NN * NN);
        for (int idx = tid; idx < 128 * 64; idx += NTH) {
            int i = idx >> 6, p = idx & 63;
            int2 av = arow[i * 64 + p];
            unsigned w = (av.x ? 0x3F80u : 0u) | (av.y ? 0x3F800000u : 0u);
            sMB[i * HBD + p] = w;
        }
    }
    // W1[0]^T staged with lane->f mapping (store banks = f: conflict-free)
    {
        const float4* wv = (const float4*)(w1);
        for (int i = tid; i < 4096; i += NTH) {
            int head = i >> 9, o4 = (i >> 7) & 3, f = i & 127;
            float4 v = wv[head * 512 + f * 4 + o4];
            int c = head * 16 + o4 * 4;
            sW[(c + 0) * SD + f] = tf32r(v.x);
            sW[(c + 1) * SD + f] = tf32r(v.y);
            sW[(c + 2) * SD + f] = tf32r(v.z);
            sW[(c + 3) * SD + f] = tf32r(v.w);
        }
    }
    if (tid < 128) { sP1S[tid] = a_src1[tid]; sP1D[tid] = a_dst1[tid]; }
    if (tid < 16)  sB1[tid] = b1[tid];
    if (tid < 256) { int f = tid >> 1, o = tid & 1; sW2T[o * 128 + f] = w2[tid]; }
    if (tid == 0) {
        sMISC[0] = a_src2[0]; sMISC[1] = a_src2[1];
        sMISC[2] = a_dst2[0]; sMISC[3] = a_dst2[1];
        sMISC[8] = b2[0];     sMISC[9] = b2[1];
    }

    // ================= MC-sample loop ==========================================
    for (int s = 0; s < S_MC; s++) {
        __syncthreads();   // staging (init or prior overlap) visible

        // ---- GEMM1 (tf32 tensor, k-outer): hT[c][n] = sum_f wT[c][f] x0[n][f] ----
        {
            const int ct = (warp >> 2) * 16;
            const int ra = ct + g, rb = ra + 8;
            const float* wra = sW + ra * SD;
            const float* wrb = sW + rb * SD;
            const int nbase = (warp & 3) * 8;
            float acc[4][4];
#pragma unroll
            for (int q = 0; q < 4; q++)
#pragma unroll
                for (int c = 0; c < 4; c++) acc[q][c] = 0.f;

#pragma unroll
            for (int t = 0; t < 8; t++) {
                const int o = 16 * t + 4 * l3;
                const float4 A0 = *(const float4*)&wra[o];
                const float4 A1 = *(const float4*)&wrb[o];
#pragma unroll
                for (int q = 0; q < 4; q++) {
                    const int n0 = nbase + 32 * q;
                    const float4 Bv = *(const float4*)&sX0[(n0 + g) * SD + o];
                    MMA_TF32(acc[q][0], acc[q][1], acc[q][2], acc[q][3],
                             __float_as_uint(A0.x), __float_as_uint(A1.x),
                             __float_as_uint(A0.y), __float_as_uint(A1.y),
                             __float_as_uint(Bv.x), __float_as_uint(Bv.y));
                    MMA_TF32(acc[q][0], acc[q][1], acc[q][2], acc[q][3],
                             __float_as_uint(A0.z), __float_as_uint(A1.z),
                             __float_as_uint(A0.w), __float_as_uint(A1.w),
                             __float_as_uint(Bv.z), __float_as_uint(Bv.w));
                }
            }
#pragma unroll
            for (int q = 0; q < 4; q++) {
                const int n0 = nbase + 32 * q;
                unsigned wa, wb;
                PACKBF(wa, acc[q][1], acc[q][0]);
                PACKBF(wb, acc[q][3], acc[q][2]);
                sHB[ra * HBD + (n0 >> 1) + l3] = wa;
                sHB[rb * HBD + (n0 >> 1) + l3] = wb;
            }
        }
        __syncthreads();

        // ---- att projections from bf16 h -> packed interleaved exp factors ----
        {
            const int head = tid >> 7, n = tid & 127;
            const unsigned* hw = sHB + (head * 16) * HBD + (n >> 1);
            const int amt = (1 - (n & 1)) * 16;
            float sa = 0.0f, da = 0.0f;
#pragma unroll
            for (int o = 0; o < 16; o++) {
                unsigned w = hw[o * HBD];
                float t = tanh_fast(__uint_as_float((w << amt) & 0xFFFF0000u));
                sa += t * sP1S[head * 16 + o];
                da += t * sP1D[head * 16 + o];
            }
            float ed  = __expf(da);
            float ed2 = __expf(0.2f * da);
            float es  = __expf(sa);
            float es2 = __expf(0.2f * sa);
            float edn  = __shfl_down_sync(0xffffffffu, ed, 1);
            float ed2n = __shfl_down_sync(0xffffffffu, ed2, 1);
            float esn  = __shfl_down_sync(0xffffffffu, es, 1);
            float es2n = __shfl_down_sync(0xffffffffu, es2, 1);
            if (!(n & 1)) {
                unsigned w1p, w2p;
                PACKBF(w1p, edn,  ed);
                PACKBF(w2p, ed2n, ed2);
                sEI[head * 64 + (n >> 1)] = (ull)w1p | ((ull)w2p << 32);
                PACKBF(w1p, esn,  es);
                PACKBF(w2p, es2n, es2);
                sSI[head * 64 + (n >> 1)] = (ull)w1p | ((ull)w2p << 32);
            }
        }
        __syncthreads();

        // ---- flash-style AV: 64 jobs, bf16 m16n8k16; row sums via ones-MMA ----
        {
            for (int job = warp; job < 64; job += 32) {
                const int head = job >> 3, rt = job & 7;
                const int i0 = rt * 16;
                const int ra = i0 + g, rb = ra + 8;
                const unsigned sel = (g & 1) ? 0x3232u : 0x1010u;
                const ull sw0 = sSI[head * 64 + (ra >> 1)];
                const ull sw1 = sSI[head * 64 + (ra >> 1) + 4];
                unsigned EsA, Es2A, EsB, Es2B;
                PRMT(EsA,  (unsigned)sw0,         sel);
                PRMT(Es2A, (unsigned)(sw0 >> 32), sel);
                PRMT(EsB,  (unsigned)sw1,         sel);
                PRMT(Es2B, (unsigned)(sw1 >> 32), sel);
                float cA0 = 0.f, cA1 = 0.f, cA2 = 0.f, cA3 = 0.f;
                float cB0 = 0.f, cB1 = 0.f, cB2 = 0.f, cB3 = 0.f;
                float cS0 = 0.f, cS1 = 0.f, cS2 = 0.f, cS3 = 0.f;
                const ull* EIh = sEI + head * 64;
                const unsigned* MA  = sMB + ra * HBD;
                const unsigned* MBp = sMB + rb * HBD;
                const unsigned* H0  = sHB + (head * 16 + g) * HBD;
                const unsigned* H1p = sHB + (head * 16 + 8 + g) * HBD;
#pragma unroll
                for (int t = 0; t < 8; t++) {
                    const int p0 = 8 * t + l3, p1 = p0 + 4;
                    const ull e0w = EIh[p0], e1w = EIh[p1];
                    const unsigned eb0 = (unsigned)e0w, e20 = (unsigned)(e0w >> 32);
                    const unsigned eb1 = (unsigned)e1w, e21 = (unsigned)(e1w >> 32);
                    const unsigned ma0 = MA[p0],  ma1 = MA[p1];
                    const unsigned mb0 = MBp[p0], mb1 = MBp[p1];
                    unsigned t0, t1, a0, a1, a2, a3;
                    HMUL2B(t0, EsA, eb0); HMUL2B(t1, Es2A, e20);
                    HMAX2B(a0, t0, t1);   HMUL2B(a0, a0, ma0);
                    HMUL2B(t0, EsB, eb0); HMUL2B(t1, Es2B, e20);
                    HMAX2B(a1, t0, t1);   HMUL2B(a1, a1, mb0);
                    HMUL2B(t0, EsA, eb1); HMUL2B(t1, Es2A, e21);
                    HMAX2B(a2, t0, t1);   HMUL2B(a2, a2, ma1);
                    HMUL2B(t0, EsB, eb1); HMUL2B(t1, Es2B, e21);
                    HMAX2B(a3, t0, t1);   HMUL2B(a3, a3, mb1);
                    const unsigned h00 = H0[p0], h01 = H0[p1];
                    const unsigned h10 = H1p[p0], h11 = H1p[p1];
                    MMA_BF16(cA0, cA1, cA2, cA3, a0, a1, a2, a3, h00, h01);
                    MMA_BF16(cB0, cB1, cB2, cB3, a0, a1, a2, a3, h10, h11);
                    MMA_BF16(cS0, cS1, cS2, cS3, a0, a1, a2, a3, ONES2, ONES2);
                }
                const float inva = 1.0f / cS0;
                const float invb = 1.0f / cS2;
                const int cl0 = l3 * 2;
                const float bi00 = sB1[cl0], bi01 = sB1[cl0 + 1];
                const float bi10 = sB1[cl0 + 8], bi11 = sB1[cl0 + 9];
                const int c0c = head * 16;
                *(float2*)&sW[ra * XSD + c0c + cl0] =
                    make_float2(elu_f(cA0 * inva + bi00), elu_f(cA1 * inva + bi01));
                *(float2*)&sW[ra * XSD + c0c + 8 + cl0] =
                    make_float2(elu_f(cB0 * inva + bi10), elu_f(cB1 * inva + bi11));
                *(float2*)&sW[rb * XSD + c0c + cl0] =
                    make_float2(elu_f(cA2 * invb + bi00), elu_f(cA3 * invb + bi01));
                *(float2*)&sW[rb * XSD + c0c + 8 + cl0] =
                    make_float2(elu_f(cB2 * invb + bi10), elu_f(cB3 * invb + bi11));
            }
        }
        __syncthreads();

        // ---- layer 2 linear: h2[n][0:2], interleaved f split (conflict-free) ----
        {
            const int n = tid >> 3, fs = tid & 7;
            const float* xr = sW + n * XSD + fs * 2;
            const ull* w2o0 = (const ull*)&sW2T[0 * 128];
            const ull* w2o1 = (const ull*)&sW2T[1 * 128];
            ull acc0 = 0ULL, acc1 = 0ULL;
#pragma unroll
            for (int fp = 0; fp < 8; fp++) {
                const ull xp = *(const ull*)&xr[fp * 16];
                FFMA2(acc0, xp, w2o0[fs + fp * 8], acc0);
                FFMA2(acc1, xp, w2o1[fs + fp * 8], acc1);
            }
            float l0, h0, l1, h1;
            UNPK2(l0, h0, acc0); UNPK2(l1, h1, acc1);
            float p0 = l0 + h0, p1 = l1 + h1;
#pragma unroll
            for (int d = 4; d > 0; d >>= 1) {
                p0 += __shfl_xor_sync(0xffffffffu, p0, d);
                p1 += __shfl_xor_sync(0xffffffffu, p1, d);
            }
            if (fs == 0) { sH2[2 * n] = p0; sH2[2 * n + 1] = p1; }
        }
        __syncthreads();

        // ---- split phase: warp 0 does tanh+ego in registers; warps 1-31 stage s+1
        if (warp == 0) {
            const int sl = (s & 1) * 4;
            const float as20 = sMISC[sl + 0], as21 = sMISC[sl + 1];
            const float ad20 = sMISC[sl + 2], ad21 = sMISC[sl + 3];
            float dst2r[4], srcv = 0.0f;
#pragma unroll
            for (int gg = 0; gg < 4; gg++) {
                int n = gg * 32 + lane;
                float t0 = tanh_fast(sH2[2 * n]);
                float t1 = tanh_fast(sH2[2 * n + 1]);
                dst2r[gg] = t0 * ad20 + t1 * ad21;
                if (gg == 3) srcv = t0 * as20 + t1 * as21;   // lane31 holds n=127
            }
            srcv = __shfl_sync(0xffffffffu, srcv, 31);
            float sum = 0.0f, a0 = 0.0f, a1 = 0.0f;
            const int amt = (1 - (lane & 1)) * 16;
#pragma unroll
            for (int gg = 0; gg < 4; gg++) {
                int j = gg * 32 + lane;
                float v = srcv + dst2r[gg];
                v = fmaxf(v, 0.2f * v);
                unsigned mw = sMB[127 * HBD + (j >> 1)];
                float mf = __uint_as_float((mw << amt) & 0xFFFF0000u);
                float e = __expf(v) * mf;
                sum += e;
                a0 += e * sH2[2 * j];
                a1 += e * sH2[2 * j + 1];
            }
#pragma unroll
            for (int d = 16; d > 0; d >>= 1) {
                sum += __shfl_xor_sync(0xffffffffu, sum, d);
                a0  += __shfl_xor_sync(0xffffffffu, a0, d);
                a1  += __shfl_xor_sync(0xffffffffu, a1, d);
            }
            if (lane == 0) {
                float inv = 1.0f / sum;
                float o0 = a0 * inv + sMISC[8];
                float o1 = a1 * inv + sMISC[9];
                float mm  = fmaxf(o0, o1);
                float lse = mm + logf(expf(o0 - mm) + expf(o1 - mm));
                if (s == 0) { sMISC[10] = o0 - lse;  sMISC[11] = o1 - lse; }
                else        { sMISC[10] += o0 - lse; sMISC[11] += o1 - lse; }
            }
        } else if (s < S_MC - 1) {
            // stage W1[s+1]^T (lane->f mapping, conflict-free stores) + params
            const float4* wv = (const float4*)(w1 + (size_t)(s + 1) * H1 * 128 * F1);
            for (int i = tid - 32; i < 4096; i += NTH - 32) {
                int head = i >> 9, o4 = (i >> 7) & 3, f = i & 127;
                float4 v = wv[head * 512 + f * 4 + o4];
                int c = head * 16 + o4 * 4;
                sW[(c + 0) * SD + f] = tf32r(v.x);
                sW[(c + 1) * SD + f] = tf32r(v.y);
                sW[(c + 2) * SD + f] = tf32r(v.z);
                sW[(c + 3) * SD + f] = tf32r(v.w);
            }
            if (tid >= 32 && tid < 160) {
                int q = tid - 32;
                sP1S[q] = a_src1[(s + 1) * 128 + q];
                sP1D[q] = a_dst1[(s + 1) * 128 + q];
            }
            if (tid >= 160 && tid < 416) {
                int q = tid - 160, f = q >> 1, o = q & 1;
                sW2T[o * 128 + f] = w2[(s + 1) * 256 + q];
            }
            if (tid == 32) {
                int sl = ((s + 1) & 1) * 4;
                sMISC[sl + 0] = a_src2[(s + 1) * 2 + 0];
                sMISC[sl + 1] = a_src2[(s + 1) * 2 + 1];
                sMISC[sl + 2] = a_dst2[(s + 1) * 2 + 0];
                sMISC[sl + 3] = a_dst2[(s + 1) * 2 + 1];
            }
        }
        // loop-top __syncthreads() protects sW and params for the next iteration
    }

    // ---- final: mean over S (accumulators written by tid 0 itself) ----
    if (tid == 0) {
        out[b * 2 + 0] = 0.25f * sMISC[10];
        out[b * 2 + 1] = 0.25f * sMISC[11];
    }
}

extern "C" void kernel_launch(void* const* d_in, const int* in_sizes, int n_in,
                              void* d_out, int out_size)
{
    const float* x      = (const float*)d_in[0];
    const float* emb    = (const float*)d_in[1];
    const int*   adj    = (const int*)d_in[2];
    const float* w1     = (const float*)d_in[3];
    const float* a_src1 = (const float*)d_in[4];
    const float* a_dst1 = (const float*)d_in[5];
    const float* b1     = (const float*)d_in[6];
    const float* w2     = (const float*)d_in[7];
    const float* a_src2 = (const float*)d_in[8];
    const float* a_dst2 = (const float*)d_in[9];
    const float* b2     = (const float*)d_in[10];

    cudaFuncSetAttribute(gat_fused_kernel,
                         cudaFuncAttributeMaxDynamicSharedMemorySize, SMEM_BYTES);

    gat_fused_kernel<<<BATCH, NTH, SMEM_BYTES>>>(
        x, emb, adj, w1, a_src1, a_dst1, b1, w2, a_src2, a_dst2, b2,
        (float*)d_out);
}